// round 13
// baseline (speedup 1.0000x reference)
#include <cuda_runtime.h>
#include <stdint.h>

// TwoHotEmbedding: out[t,:] = w[i1[t],:]              if i1[t]==i2[t]
//                             w[i1[t],:] + w[i2[t],:]  otherwise
// B*S = 65536 tokens, D = 256 floats per row (1024 B = 32 lanes x 32 B).
//
// FINAL (converged, R1-R12): kernel is pinned at the path-independent chip
// LTS cap (~200 MB SM<->L2 crossing @ ~8.3 TB/s). All mechanistic levers
// tested and bounded: load width, cache hints, store width/policy, epilogue
// form, occupancy 58-81%, CTA/grid shape, persistence. This exact binary
// produced the best e2e twice (26.656us, R4 and R9); every deviation
// measured >= 27.1us. One-shot 2 tokens/warp, 4 independent 256-bit
// evict_last gathers in flight, paired 128-bit .cs streaming stores,
// branch-free select epilogue, 256-thread CTAs, grid 4096.

struct V8 { float v[8]; };

__device__ __forceinline__ V8 ldg256_keep(const float* p) {
    V8 r;
    asm volatile(
        "ld.global.nc.L2::evict_last.v8.b32 {%0,%1,%2,%3,%4,%5,%6,%7}, [%8];"
        : "=f"(r.v[0]), "=f"(r.v[1]), "=f"(r.v[2]), "=f"(r.v[3]),
          "=f"(r.v[4]), "=f"(r.v[5]), "=f"(r.v[6]), "=f"(r.v[7])
        : "l"(p));
    return r;
}

__device__ __forceinline__ void stg_stream4(float* p, float a, float b, float c, float d) {
    asm volatile("st.global.cs.v4.f32 [%0], {%1,%2,%3,%4};"
                 :: "l"(p), "f"(a), "f"(b), "f"(c), "f"(d)
                 : "memory");
}

__global__ __launch_bounds__(256) void twohot_kernel(
    const int* __restrict__ idx1,
    const int* __restrict__ idx2,
    const float* __restrict__ weight,   // [NUM_EMB, 256] f32
    float* __restrict__ out,            // [tokens, 256] f32
    int n_tokens)
{
    const int warp_global = (blockIdx.x * blockDim.x + threadIdx.x) >> 5;
    const int lane = threadIdx.x & 31;
    const int t0 = warp_global * 2;            // first of 2 tokens
    if (t0 >= n_tokens) return;

    // Paired index loads (64-bit each, warp-broadcast).
    const int2 ia = *(const int2*)(idx1 + t0);
    const int2 ib = *(const int2*)(idx2 + t0);

    const int off = lane * 8;
    const float* p1a = weight + (size_t)ia.x * 256 + off;
    const float* p2a = weight + (size_t)ib.x * 256 + off;
    const float* p1b = weight + (size_t)ia.y * 256 + off;
    const float* p2b = weight + (size_t)ib.y * 256 + off;

    // 4 independent 256-bit gathers in flight.
    V8 e1a = ldg256_keep(p1a);
    V8 e2a = ldg256_keep(p2a);
    V8 e1b = ldg256_keep(p1b);
    V8 e2b = ldg256_keep(p2b);

    // i1==i2 has probability ~1e-5: handle with selects, no divergence.
    const bool same_a = (ia.x == ib.x);
    const bool same_b = (ia.y == ib.y);

    float ra[8], rb[8];
    #pragma unroll
    for (int i = 0; i < 8; i++) {
        ra[i] = same_a ? e1a.v[i] : e1a.v[i] + e2a.v[i];
        rb[i] = same_b ? e1b.v[i] : e1b.v[i] + e2b.v[i];
    }

    float* oa = out + (size_t)t0 * 256 + off;
    float* ob = oa + 256;
    stg_stream4(oa,     ra[0], ra[1], ra[2], ra[3]);
    stg_stream4(oa + 4, ra[4], ra[5], ra[6], ra[7]);
    stg_stream4(ob,     rb[0], rb[1], rb[2], rb[3]);
    stg_stream4(ob + 4, rb[4], rb[5], rb[6], rb[7]);
}

extern "C" void kernel_launch(void* const* d_in, const int* in_sizes, int n_in,
                              void* d_out, int out_size)
{
    const int* idx1 = (const int*)d_in[0];        // input_one [B,S] int32
    const int* idx2 = (const int*)d_in[1];        // input_two [B,S] int32
    const float* weight = (const float*)d_in[2];  // weight [100000,256] f32

    float* out = (float*)d_out;

    const int n_tokens = in_sizes[0];             // 65536
    (void)n_in; (void)out_size;

    // 8 warps/block, 2 tokens/warp -> 16 tokens per block -> 4096 blocks.
    const int tokens_per_block = 16;
    const int blocks = (n_tokens + tokens_per_block - 1) / tokens_per_block;
    twohot_kernel<<<blocks, 256>>>(idx1, idx2, weight, out, n_tokens);
}

// round 14
// speedup vs baseline: 1.0012x; 1.0012x over previous
#include <cuda_runtime.h>
#include <stdint.h>

// TwoHotEmbedding: out[t,:] = w[i1[t],:]              if i1[t]==i2[t]
//                             w[i1[t],:] + w[i2[t],:]  otherwise
// B*S = 65536 tokens, D = 256 floats per row (1024 B = 32 lanes x 32 B).
//
// Converged model (R1-R13): kernel pinned at the path-independent chip LTS
// cap (~200 MB SM<->L2 crossing @ ~8.3 TB/s => ~24us kernel floor), with
// +/-0.7us run-to-run noise (NAT DVFS) exceeding all remaining levers.
// R14 = minimum-instruction combination of the two best kernel-time
// observations: 1 token/warp (24.26us twice, most consistent) + R10's
// lean epilogue/store (24.10us, single best). Per token per lane:
// 2x LDG.256 (evict_last) + 8 FFMA (mask in {0,1}) + 1x STG.256 (.cs).

struct V8 { float v[8]; };

__device__ __forceinline__ V8 ldg256_keep(const float* p) {
    V8 r;
    asm volatile(
        "ld.global.nc.L2::evict_last.v8.b32 {%0,%1,%2,%3,%4,%5,%6,%7}, [%8];"
        : "=f"(r.v[0]), "=f"(r.v[1]), "=f"(r.v[2]), "=f"(r.v[3]),
          "=f"(r.v[4]), "=f"(r.v[5]), "=f"(r.v[6]), "=f"(r.v[7])
        : "l"(p));
    return r;
}

__device__ __forceinline__ void stg256_stream(float* p, const float* r) {
    asm volatile(
        "st.global.cs.v8.b32 [%0], {%1,%2,%3,%4,%5,%6,%7,%8};"
        :: "l"(p),
           "f"(r[0]), "f"(r[1]), "f"(r[2]), "f"(r[3]),
           "f"(r[4]), "f"(r[5]), "f"(r[6]), "f"(r[7])
        : "memory");
}

__global__ __launch_bounds__(256) void twohot_kernel(
    const int* __restrict__ idx1,
    const int* __restrict__ idx2,
    const float* __restrict__ weight,   // [NUM_EMB, 256] f32
    float* __restrict__ out,            // [tokens, 256] f32
    int n_tokens)
{
    const int t = (blockIdx.x * blockDim.x + threadIdx.x) >> 5;  // 1 token/warp
    const int lane = threadIdx.x & 31;
    if (t >= n_tokens) return;

    // Warp-uniform index loads (broadcast).
    const int a = idx1[t];
    const int b = idx2[t];

    const int off = lane * 8;                  // 8 floats = 32 B per lane
    const float* pa = weight + (size_t)a * 256 + off;
    const float* pb = weight + (size_t)b * 256 + off;

    // 2 independent 256-bit gathers in flight.
    V8 ea = ldg256_keep(pa);
    V8 eb = ldg256_keep(pb);

    // i1==i2 (prob ~1e-5): fold into an FMA multiplier (exact: m in {0,1}).
    const float m = (a == b) ? 0.0f : 1.0f;

    float r[8];
    #pragma unroll
    for (int i = 0; i < 8; i++)
        r[i] = fmaf(m, eb.v[i], ea.v[i]);

    stg256_stream(out + (size_t)t * 256 + off, r);
}

extern "C" void kernel_launch(void* const* d_in, const int* in_sizes, int n_in,
                              void* d_out, int out_size)
{
    const int* idx1 = (const int*)d_in[0];        // input_one [B,S] int32
    const int* idx2 = (const int*)d_in[1];        // input_two [B,S] int32
    const float* weight = (const float*)d_in[2];  // weight [100000,256] f32

    float* out = (float*)d_out;

    const int n_tokens = in_sizes[0];             // 65536
    (void)n_in; (void)out_size;

    // 8 warps/block, 1 token/warp -> 8 tokens/block -> 8192 blocks.
    const int blocks = (n_tokens + 7) / 8;
    twohot_kernel<<<blocks, 256>>>(idx1, idx2, weight, out, n_tokens);
}